// round 16
// baseline (speedup 1.0000x reference)
#include <cuda_runtime.h>
#include <cuda_fp16.h>
#include <math.h>

#define Bb 2
#define Ss 2048
#define Dd 1024
#define Hh 16
#define DHh 64
#define IHh 4
#define IDd 64
#define TOPK 512
#define BT (Bb*Ss)
#define NKW 68    // packed Wk(64)|Ww(4)
#define NFUSE 3328  // 3072 (QKV) + 256 (iq)

// ---------------- scratch (device globals; no allocation allowed) ----------
__device__ float g_q[BT * Dd];            // post-RoPE Q (fp32)
__device__ __half g_kv[BT * 2 * Dd];      // [b,s, K(1024)|V(1024)] fp16
__device__ float2 g_tab[Ss * 32];         // RoPE (cos,sin) per (s, p)
__device__ float g_iq[BT * IHh * IDd];    // iq projections (3xTF32)
__device__ float g_wkw[Dd * NKW];         // packed Wk|Ww
__device__ float g_ikw[BT * NKW];         // fused ik|iw projections (exact fp32)
__device__ int   g_sel[BT * TOPK];
__device__ int   g_cnt[BT];
__device__ float g_attn[BT * Dd];

// ---------------- tf32 helpers ----------------------------------------------
__device__ __forceinline__ unsigned t32h(float f) {
    unsigned u;
    asm("cvt.rna.tf32.f32 %0, %1;" : "=r"(u) : "f"(f));
    return u;
}
__device__ __forceinline__ unsigned t32l(float f, unsigned h) {
    float r = f - __uint_as_float(h);
    unsigned u;
    asm("cvt.rna.tf32.f32 %0, %1;" : "=r"(u) : "f"(r));
    return u;
}

#define MMA_TF32(ac, A0,A1,A2,A3, B0,B1)                                       \
    asm volatile("mma.sync.aligned.m16n8k8.row.col.f32.tf32.tf32.f32 "         \
                 "{%0,%1,%2,%3}, {%4,%5,%6,%7}, {%8,%9}, {%0,%1,%2,%3};"       \
                 : "+f"(ac[0]), "+f"(ac[1]), "+f"(ac[2]), "+f"(ac[3])          \
                 : "r"(A0), "r"(A1), "r"(A2), "r"(A3), "r"(B0), "r"(B1))

#define CP16(smem_u32, gptr)                                                   \
    asm volatile("cp.async.cg.shared.global [%0], [%1], 16;"                   \
                 :: "r"(smem_u32), "l"(gptr))

// ---------------- RoPE cos/sin table ----------------------------------------
__global__ __launch_bounds__(256) void rope_table(float2* __restrict__ tab) {
    int idx = blockIdx.x * 256 + threadIdx.x;
    if (idx >= Ss * 32) return;
    int s = idx >> 5, p = idx & 31;
    double theta = pow(10000.0, -(2.0 * p) / 64.0);
    float ang = (float)((double)s * theta);
    float sn, cn;
    sincosf(ang, &sn, &cn);
    tab[idx] = make_float2(cn, sn);
}

// ---------------- TF32 tensor-core GEMM, cp.async double-buffered ----------
// (frozen since R8/R13/R14 — do not touch numerics)
template<bool PRECISE, int EPI>
__global__ __launch_bounds__(256, 2) void gemm_tc(const float* __restrict__ A,
                                                  const float* __restrict__ B,
                                                  float* __restrict__ C,
                                                  int M, int N, int K,
                                                  const float2* __restrict__ tab,
                                                  __half* __restrict__ kvp,
                                                  const float* __restrict__ B2,
                                                  float* __restrict__ C2) {
    __shared__ __align__(16) float As[2][128 * 20];
    __shared__ __align__(16) float Bs[2][16 * 136];
    int tid = threadIdx.x;
    int lane = tid & 31, warp = tid >> 5;
    int g = lane >> 2, tg = lane & 3;
    int wm0 = (warp & 1) * 64, wn0 = (warp >> 1) * 32;
    int m0 = blockIdx.y * 128, n0 = blockIdx.x * 128;

    const float* Bp = B;
    int Nb = (EPI == 1) ? 3072 : N;
    int nb0 = n0;
    if (EPI == 1 && n0 >= 3072) { Bp = B2; Nb = 256; nb0 = n0 - 3072; }

    unsigned sA0 = (unsigned)__cvta_generic_to_shared(&As[0][0]);
    unsigned sB0 = (unsigned)__cvta_generic_to_shared(&Bs[0][0]);

    float acc[4][4][4];
    #pragma unroll
    for (int mi = 0; mi < 4; mi++)
        #pragma unroll
        for (int nj = 0; nj < 4; nj++)
            #pragma unroll
            for (int q = 0; q < 4; q++) acc[mi][nj][q] = 0.f;

    const int nK = K / 16;

    #define LOAD_STAGE(st, k0)                                                 \
        do {                                                                   \
            _Pragma("unroll")                                                  \
            for (int it = 0; it < 2; it++) {                                   \
                int i = tid + it * 256;                                        \
                int r = i >> 2, kk = (i & 3) * 4;                              \
                CP16(sA0 + ((st) * 2560 + r * 20 + kk) * 4,                    \
                     A + (size_t)(m0 + r) * K + (k0) + kk);                    \
                int bk = i >> 5, n4 = (i & 31) * 4;                            \
                CP16(sB0 + ((st) * 2176 + bk * 136 + n4) * 4,                  \
                     Bp + (size_t)((k0) + bk) * Nb + nb0 + n4);                \
            }                                                                  \
        } while (0)

    LOAD_STAGE(0, 0);
    asm volatile("cp.async.commit_group;");

    for (int ks = 0; ks < nK; ks++) {
        int cur = ks & 1;
        if (ks + 1 < nK) {
            LOAD_STAGE(cur ^ 1, (ks + 1) * 16);
            asm volatile("cp.async.commit_group;");
            asm volatile("cp.async.wait_group 1;");
        } else {
            asm volatile("cp.async.wait_group 0;");
        }
        __syncthreads();

        const float* as = As[cur];
        const float* bs = Bs[cur];
        #pragma unroll
        for (int kc = 0; kc < 16; kc += 8) {
            unsigned ah[4][4], al[4][4];
            unsigned bh[4][2], bl[4][2];
            #pragma unroll
            for (int mi = 0; mi < 4; mi++) {
                int r = wm0 + mi * 16 + g;
                float v0 = as[r * 20 + kc + tg];
                float v1 = as[(r + 8) * 20 + kc + tg];
                float v2 = as[r * 20 + kc + tg + 4];
                float v3 = as[(r + 8) * 20 + kc + tg + 4];
                ah[mi][0] = t32h(v0); ah[mi][1] = t32h(v1);
                ah[mi][2] = t32h(v2); ah[mi][3] = t32h(v3);
                if (PRECISE) {
                    al[mi][0] = t32l(v0, ah[mi][0]); al[mi][1] = t32l(v1, ah[mi][1]);
                    al[mi][2] = t32l(v2, ah[mi][2]); al[mi][3] = t32l(v3, ah[mi][3]);
                }
            }
            #pragma unroll
            for (int nj = 0; nj < 4; nj++) {
                int c = wn0 + nj * 8 + g;
                float v0 = bs[(kc + tg) * 136 + c];
                float v1 = bs[(kc + tg + 4) * 136 + c];
                bh[nj][0] = t32h(v0); bh[nj][1] = t32h(v1);
                if (PRECISE) {
                    bl[nj][0] = t32l(v0, bh[nj][0]);
                    bl[nj][1] = t32l(v1, bh[nj][1]);
                }
            }
            #pragma unroll
            for (int mi = 0; mi < 4; mi++)
                #pragma unroll
                for (int nj = 0; nj < 4; nj++) {
                    MMA_TF32(acc[mi][nj], ah[mi][0], ah[mi][1], ah[mi][2], ah[mi][3],
                             bh[nj][0], bh[nj][1]);
                    if (PRECISE) {
                        MMA_TF32(acc[mi][nj], ah[mi][0], ah[mi][1], ah[mi][2], ah[mi][3],
                                 bl[nj][0], bl[nj][1]);
                        MMA_TF32(acc[mi][nj], al[mi][0], al[mi][1], al[mi][2], al[mi][3],
                                 bh[nj][0], bh[nj][1]);
                    }
                }
        }
        __syncthreads();
    }
    #undef LOAD_STAGE

    if (EPI == 0) {
        #pragma unroll
        for (int mi = 0; mi < 4; mi++) {
            int r = m0 + wm0 + mi * 16 + g;
            #pragma unroll
            for (int nj = 0; nj < 4; nj++) {
                int c = n0 + wn0 + nj * 8 + tg * 2;
                *(float2*)&C[(size_t)r * N + c] = make_float2(acc[mi][nj][0], acc[mi][nj][1]);
                *(float2*)&C[(size_t)(r + 8) * N + c] = make_float2(acc[mi][nj][2], acc[mi][nj][3]);
            }
        }
    } else {
        int region = n0 >> 10;   // 0=Q, 1=K, 2=V, 3=iq
        #pragma unroll
        for (int mi = 0; mi < 4; mi++) {
            int r = m0 + wm0 + mi * 16 + g;
            int s = r & 2047;
            #pragma unroll
            for (int nj = 0; nj < 4; nj++) {
                int c = n0 + wn0 + nj * 8 + tg * 2;
                float a0 = acc[mi][nj][0], a1 = acc[mi][nj][1];
                float a2 = acc[mi][nj][2], a3 = acc[mi][nj][3];
                if (region == 3) {
                    int cc = c - 3072;
                    *(float2*)&C2[(size_t)r * 256 + cc] = make_float2(a0, a1);
                    *(float2*)&C2[(size_t)(r + 8) * 256 + cc] = make_float2(a2, a3);
                } else if (region == 2) {
                    int cc = c & 1023;
                    *(__half2*)(kvp + (size_t)r * 2048 + 1024 + cc) = __floats2half2_rn(a0, a1);
                    *(__half2*)(kvp + (size_t)(r + 8) * 2048 + 1024 + cc) = __floats2half2_rn(a2, a3);
                } else {
                    int cc = c & 1023;
                    int p = (cc & 63) >> 1;
                    float2 t0 = tab[s * 32 + p];
                    float2 t1 = tab[(s + 8) * 32 + p];
                    float y0 = a0 * t0.x - a1 * t0.y;
                    float y1 = a1 * t0.x + a0 * t0.y;
                    float y2 = a2 * t1.x - a3 * t1.y;
                    float y3 = a3 * t1.x + a2 * t1.y;
                    if (region == 0) {
                        *(float2*)&C[(size_t)r * 1024 + cc] = make_float2(y0, y1);
                        *(float2*)&C[(size_t)(r + 8) * 1024 + cc] = make_float2(y2, y3);
                    } else {
                        *(__half2*)(kvp + (size_t)r * 2048 + cc) = __floats2half2_rn(y0, y1);
                        *(__half2*)(kvp + (size_t)(r + 8) * 2048 + cc) = __floats2half2_rn(y2, y3);
                    }
                }
            }
        }
    }
}

// ---------------- scalar fp32 SGEMM (exact): ik (cols 0..63 of ikw) --------
__global__ __launch_bounds__(256) void sgemm(const float* __restrict__ A,
                                             const float* __restrict__ B,
                                             float* __restrict__ C,
                                             int M, int N, int K) {
    __shared__ float As[64][17];
    __shared__ float Bs[16][64];
    int tid = threadIdx.x;
    int tx = tid & 15, ty = tid >> 4;
    int row0 = blockIdx.y * 64, col0 = blockIdx.x * 64;
    float acc[4][4] = {};
    for (int k0 = 0; k0 < K; k0 += 16) {
        #pragma unroll
        for (int i = 0; i < 4; i++) {
            int idx = tid + i * 256;
            int r = idx >> 4, kk = idx & 15;
            As[r][kk] = A[(size_t)(row0 + r) * K + k0 + kk];
        }
        #pragma unroll
        for (int i = 0; i < 4; i++) {
            int idx = tid + i * 256;
            int kk = idx >> 6, c = idx & 63;
            int col = col0 + c;
            Bs[kk][c] = (col < N) ? B[(size_t)(k0 + kk) * N + col] : 0.f;
        }
        __syncthreads();
        #pragma unroll
        for (int kk = 0; kk < 16; kk++) {
            float a[4], b[4];
            #pragma unroll
            for (int i = 0; i < 4; i++) a[i] = As[ty * 4 + i][kk];
            #pragma unroll
            for (int j = 0; j < 4; j++) b[j] = Bs[kk][tx * 4 + j];
            #pragma unroll
            for (int i = 0; i < 4; i++)
                #pragma unroll
                for (int j = 0; j < 4; j++)
                    acc[i][j] += a[i] * b[j];
        }
        __syncthreads();
    }
    #pragma unroll
    for (int i = 0; i < 4; i++) {
        int r = row0 + ty * 4 + i;
        #pragma unroll
        for (int j = 0; j < 4; j++) {
            int c = col0 + tx * 4 + j;
            if (c < N) C[(size_t)r * N + c] = acc[i][j];
        }
    }
}

// ---------------- iw projection micro-kernel (bit-identical seq. fmaf) -----
__global__ __launch_bounds__(256) void iw_proj(const float* __restrict__ x,
                                               const float* __restrict__ Ww,
                                               float* __restrict__ ikw) {
    int idx = blockIdx.x * 256 + threadIdx.x;
    if (idx >= BT * IHh) return;
    int bt = idx >> 2, h = idx & 3;
    const float4* xr = (const float4*)(x + (size_t)bt * Dd);
    float acc = 0.f;
    for (int k4 = 0; k4 < Dd / 4; k4++) {
        float4 xv = xr[k4];
        int k = k4 * 4;
        acc = fmaf(xv.x, Ww[k * IHh + h], acc);
        acc = fmaf(xv.y, Ww[(k + 1) * IHh + h], acc);
        acc = fmaf(xv.z, Ww[(k + 2) * IHh + h], acc);
        acc = fmaf(xv.w, Ww[(k + 3) * IHh + h], acc);
    }
    ikw[(size_t)bt * NKW + 64 + h] = acc;
}

// ---------------- pack Wk|Ww -> [1024, 68] ----------------------------------
__global__ __launch_bounds__(256) void pack_wkw(const float* __restrict__ Wk,
                                                const float* __restrict__ Ww,
                                                float* __restrict__ Wkw) {
    int idx = blockIdx.x * 256 + threadIdx.x;
    if (idx >= Dd * NKW) return;
    int row = idx / NKW, col = idx - row * NKW;
    Wkw[idx] = (col < 64) ? Wk[row * 64 + col] : Ww[row * IHh + (col - 64)];
}

__device__ __forceinline__ unsigned flipf(float f) {
    unsigned u = __float_as_uint(f);
    return (u & 0x80000000u) ? ~u : (u | 0x80000000u);
}

// ---------------- indexer scores + exact causal top-k (R14 4-pass) ---------
__global__ __launch_bounds__(256) void indexer_topk(const float* __restrict__ iq,
                                                    const float* __restrict__ ikw,
                                                    int* __restrict__ sel,
                                                    int* __restrict__ cnt) {
    int bt = blockIdx.x;
    int b = bt >> 11, t = bt & 2047;
    int tid = threadIdx.x;
    int lane = tid & 31, w = tid >> 5;
    int n = t + 1;

    __shared__ float sq[IHh * IDd];
    __shared__ float sw[IHh];
    if (tid < IHh * IDd) sq[tid] = iq[(size_t)bt * IHh * IDd + tid];
    if (tid < IHh) sw[tid] = ikw[(size_t)bt * NKW + 64 + tid];

    if (n <= TOPK) {
        for (int s = tid; s < n; s += 256) sel[(size_t)bt * TOPK + s] = s;
        if (tid == 0) cnt[bt] = n;
        return;
    }
    __syncthreads();

    __shared__ float sc[Ss];
    for (int s = tid; s < n; s += 256) {
        const float4* k4 = (const float4*)(ikw + (size_t)(b * Ss + s) * NKW);
        float d0 = 0.f, d1 = 0.f, d2 = 0.f, d3 = 0.f;
        #pragma unroll
        for (int j4 = 0; j4 < 16; j4++) {
            float4 kv = k4[j4];
            int o = j4 * 4;
            d0 += sq[0*64+o]*kv.x + sq[0*64+o+1]*kv.y + sq[0*64+o+2]*kv.z + sq[0*64+o+3]*kv.w;
            d1 += sq[1*64+o]*kv.x + sq[1*64+o+1]*kv.y + sq[1*64+o+2]*kv.z + sq[1*64+o+3]*kv.w;
            d2 += sq[2*64+o]*kv.x + sq[2*64+o+1]*kv.y + sq[2*64+o+2]*kv.z + sq[2*64+o+3]*kv.w;
            d3 += sq[3*64+o]*kv.x + sq[3*64+o+1]*kv.y + sq[3*64+o+2]*kv.z + sq[3*64+o+3]*kv.w;
        }
        sc[s] = sw[0]*fmaxf(d0,0.f) + sw[1]*fmaxf(d1,0.f)
              + sw[2]*fmaxf(d2,0.f) + sw[3]*fmaxf(d3,0.f);
    }
    __syncthreads();

    __shared__ int hist[256];
    __shared__ int sfx[256];
    __shared__ unsigned sh_prefix;
    __shared__ int sh_krem;
    unsigned prefix = 0;
    int krem = TOPK;
    for (int pass = 0; pass < 4; pass++) {
        int shift = 24 - pass * 8;
        hist[tid] = 0;
        __syncthreads();
        for (int s0 = 0; s0 < n; s0 += 256) {
            int s = s0 + tid;
            bool valid = false;
            unsigned bin = 0;
            if (s < n) {
                unsigned key = flipf(sc[s]);
                if (((key >> shift) >> 8) == prefix) {
                    valid = true;
                    bin = (key >> shift) & 255;
                }
            }
            unsigned act = __ballot_sync(0xffffffffu, valid);
            if (valid) {
                unsigned peers = __match_any_sync(act, bin);
                if ((__ffs(peers) - 1) == lane)
                    atomicAdd(&hist[bin], __popc(peers));
            }
        }
        __syncthreads();
        int hv = hist[tid];
        sfx[tid] = hv;
        __syncthreads();
        #pragma unroll
        for (int off = 1; off < 256; off <<= 1) {
            int add = (tid + off < 256) ? sfx[tid + off] : 0;
            __syncthreads();
            sfx[tid] += add;
            __syncthreads();
        }
        int sf = sfx[tid];
        int sfn = (tid < 255) ? sfx[tid + 1] : 0;
        if (sf >= krem && sfn < krem) {
            sh_prefix = (prefix << 8) | (unsigned)tid;
            sh_krem = krem - sfn;
        }
        __syncthreads();
        prefix = sh_prefix;
        krem = sh_krem;
        __syncthreads();
    }
    unsigned T = prefix;

    __shared__ int nsel;
    if (tid == 0) nsel = 0;
    __syncthreads();
    for (int s = tid; s < n; s += 256) {
        if (flipf(sc[s]) > T) {
            int p = atomicAdd(&nsel, 1);
            sel[(size_t)bt * TOPK + p] = s;
        }
    }
    __syncthreads();

    __shared__ int warpcnt[8];
    __shared__ int eqbase;
    if (tid == 0) eqbase = 0;
    __syncthreads();
    for (int s0 = 0; s0 < n; s0 += 256) {
        int s = s0 + tid;
        bool eq = false;
        if (s < n) eq = (flipf(sc[s]) == T);
        unsigned bal = __ballot_sync(0xffffffffu, eq);
        if (lane == 0) warpcnt[w] = __popc(bal);
        __syncthreads();
        int wbase = 0;
        for (int i = 0; i < w; i++) wbase += warpcnt[i];
        int rank = eqbase + wbase + __popc(bal & ((1u << lane) - 1));
        if (eq && rank < krem) {
            int p = atomicAdd(&nsel, 1);
            sel[(size_t)bt * TOPK + p] = s;
        }
        __syncthreads();
        if (tid == 0) {
            int tot = 0;
            for (int i = 0; i < 8; i++) tot += warpcnt[i];
            eqbase += tot;
        }
        __syncthreads();
    }
    if (tid == 0) cnt[bt] = TOPK;
}

// ---------------- sparse SDPA: block per (b,t, head-half), warp per head ---
__global__ __launch_bounds__(256, 2) void sdpa(const float* __restrict__ qp,
                                               const __half* __restrict__ kv,
                                               const int* __restrict__ sel,
                                               const int* __restrict__ cnt,
                                               float* __restrict__ attn) {
    int bt = blockIdx.x;
    int b = bt >> 11;
    int tid = threadIdx.x;
    int w = tid >> 5, lane = tid & 31;
    int h = blockIdx.y * 8 + w;

    __shared__ float sQ[8 * DHh];
    __shared__ int   sSel[TOPK];
    __shared__ float sL[8][TOPK];

    int n = cnt[bt];
    const float* Qrow = qp + (size_t)bt * Dd + blockIdx.y * 512;
    for (int i = tid; i < 512; i += 256) sQ[i] = Qrow[i];
    for (int i = tid; i < n; i += 256) sSel[i] = sel[(size_t)bt * TOPK + i];
    __syncthreads();

    float qr[64];
    #pragma unroll
    for (int i = 0; i < 64; i += 4) {
        float4 tq = *(const float4*)&sQ[w * 64 + i];
        qr[i] = tq.x; qr[i+1] = tq.y; qr[i+2] = tq.z; qr[i+3] = tq.w;
    }

    const float scale = 0.125f;
    size_t kvbase = (size_t)b * Ss * 2048;

    for (int j0 = 0; j0 < n; j0 += 32) {
        int j = j0 + lane;
        if (j < n) {
            int s = sSel[j];
            const uint4* kp = (const uint4*)(kv + kvbase + (size_t)s * 2048 + h * 64);
            float d = 0.f;
            #pragma unroll
            for (int i = 0; i < 8; i++) {
                uint4 wv = kp[i];
                const __half2* p2 = (const __half2*)&wv;
                #pragma unroll
                for (int q = 0; q < 4; q++) {
                    float2 f = __half22float2(p2[q]);
                    d += qr[i*8 + q*2] * f.x + qr[i*8 + q*2 + 1] * f.y;
                }
            }
            sL[w][j] = d * scale;
        }
    }
    __syncwarp();

    float m = -1e30f;
    for (int j = lane; j < n; j += 32) m = fmaxf(m, sL[w][j]);
    #pragma unroll
    for (int o = 16; o; o >>= 1) m = fmaxf(m, __shfl_xor_sync(0xffffffffu, m, o));
    float sum = 0.f;
    for (int j = lane; j < n; j += 32) {
        float p = __expf(sL[w][j] - m);
        sL[w][j] = p;
        sum += p;
    }
    #pragma unroll
    for (int o = 16; o; o >>= 1) sum += __shfl_xor_sync(0xffffffffu, sum, o);
    float inv = 1.f / sum;
    __syncwarp();

    int kg = lane >> 3, dg = lane & 7;
    float acc[8] = {};
    #pragma unroll 4
    for (int j0 = 0; j0 < n; j0 += 4) {
        int j = j0 + kg;
        if (j < n) {
            float p = sL[w][j];
            int s = sSel[j];
            uint4 vv = *(const uint4*)(kv + kvbase + (size_t)s * 2048 + 1024 + h * 64 + dg * 8);
            const __half2* h2 = (const __half2*)&vv;
            #pragma unroll
            for (int q = 0; q < 4; q++) {
                float2 f = __half22float2(h2[q]);
                acc[2*q]     += p * f.x;
                acc[2*q + 1] += p * f.y;
            }
        }
    }
    #pragma unroll
    for (int q = 0; q < 8; q++) {
        acc[q] += __shfl_xor_sync(0xffffffffu, acc[q], 8);
        acc[q] += __shfl_xor_sync(0xffffffffu, acc[q], 16);
    }
    if (kg == 0) {
        size_t ob = (size_t)bt * Dd + h * 64 + dg * 8;
        float4 o0 = make_float4(acc[0] * inv, acc[1] * inv, acc[2] * inv, acc[3] * inv);
        float4 o1 = make_float4(acc[4] * inv, acc[5] * inv, acc[6] * inv, acc[7] * inv);
        *(float4*)&attn[ob]     = o0;
        *(float4*)&attn[ob + 4] = o1;
    }
}

// ---------------- launch ----------------------------------------------------
extern "C" void kernel_launch(void* const* d_in, const int* in_sizes, int n_in,
                              void* d_out, int out_size) {
    const float* x      = (const float*)d_in[0];
    const float* W_qkv  = (const float*)d_in[1];
    const float* W_o    = (const float*)d_in[2];
    const float* Wq_idx = (const float*)d_in[3];
    const float* Wk_idx = (const float*)d_in[4];
    const float* Ww_idx = (const float*)d_in[5];
    float* out = (float*)d_out;

    float *qp, *iq, *wkw, *ikw, *attn;
    float2* tab;
    __half* kv;
    int *sel, *cnt;
    cudaGetSymbolAddress((void**)&qp,   g_q);
    cudaGetSymbolAddress((void**)&kv,   g_kv);
    cudaGetSymbolAddress((void**)&tab,  g_tab);
    cudaGetSymbolAddress((void**)&iq,   g_iq);
    cudaGetSymbolAddress((void**)&wkw,  g_wkw);
    cudaGetSymbolAddress((void**)&ikw,  g_ikw);
    cudaGetSymbolAddress((void**)&attn, g_attn);
    cudaGetSymbolAddress((void**)&sel,  g_sel);
    cudaGetSymbolAddress((void**)&cnt,  g_cnt);

    const int M = BT;  // 4096

    rope_table<<<(Ss * 32 + 255) / 256, 256>>>(tab);
    pack_wkw<<<(Dd * NKW + 255) / 256, 256>>>(Wk_idx, Ww_idx, wkw);
    iw_proj<<<(BT * IHh + 255) / 256, 256>>>(x, Ww_idx, ikw);
    // Fused QKV + iq projection, RoPE + fp16 K/V epilogue
    gemm_tc<true, 1><<<dim3(NFUSE / 128, M / 128), 256>>>(
        x, W_qkv, qp, M, NFUSE, Dd, tab, kv, Wq_idx, iq);
    // ik projection: exact fp32, cols 0..63 of ikw (stride NKW)
    sgemm<<<dim3(1, M / 64), 256>>>(x, wkw, ikw, M, NKW, Dd);
    // indexer scores + top-k selection (R14 4-pass version)
    indexer_topk<<<BT, 256>>>(iq, ikw, sel, cnt);
    // sparse attention
    sdpa<<<dim3(BT, 2), 256>>>(qp, kv, sel, cnt, attn);
    // output projection (3xTF32)
    gemm_tc<true, 0><<<dim3(Dd / 128, M / 128), 256>>>(
        attn, W_o, out, M, Dd, Dd, nullptr, nullptr, nullptr, nullptr);
}

// round 17
// speedup vs baseline: 1.0809x; 1.0809x over previous
#include <cuda_runtime.h>
#include <cuda_fp16.h>
#include <math.h>

#define Bb 2
#define Ss 2048
#define Dd 1024
#define Hh 16
#define DHh 64
#define IHh 4
#define IDd 64
#define TOPK 512
#define BT (Bb*Ss)
#define NKW 68    // packed Wk(64)|Ww(4)
#define NFUSE 3328  // 3072 (QKV) + 256 (iq)

// ---------------- scratch (device globals; no allocation allowed) ----------
__device__ float g_q[BT * Dd];            // post-RoPE Q (fp32)
__device__ __half g_kv[BT * 2 * Dd];      // [b,s, K(1024)|V(1024)] fp16
__device__ float2 g_tab[Ss * 32];         // RoPE (cos,sin) per (s, p)
__device__ float g_iq[BT * IHh * IDd];    // iq projections (3xTF32)
__device__ float g_wkw[Dd * NKW];         // packed Wk|Ww
__device__ float g_ikw[BT * NKW];         // fused ik|iw projections (exact fp32)
__device__ int   g_sel[BT * TOPK];
__device__ int   g_cnt[BT];
__device__ float g_attn[BT * Dd];

// ---------------- tf32 helpers ----------------------------------------------
__device__ __forceinline__ unsigned t32h(float f) {
    unsigned u;
    asm("cvt.rna.tf32.f32 %0, %1;" : "=r"(u) : "f"(f));
    return u;
}
__device__ __forceinline__ unsigned t32l(float f, unsigned h) {
    float r = f - __uint_as_float(h);
    unsigned u;
    asm("cvt.rna.tf32.f32 %0, %1;" : "=r"(u) : "f"(r));
    return u;
}

#define MMA_TF32(ac, A0,A1,A2,A3, B0,B1)                                       \
    asm volatile("mma.sync.aligned.m16n8k8.row.col.f32.tf32.tf32.f32 "         \
                 "{%0,%1,%2,%3}, {%4,%5,%6,%7}, {%8,%9}, {%0,%1,%2,%3};"       \
                 : "+f"(ac[0]), "+f"(ac[1]), "+f"(ac[2]), "+f"(ac[3])          \
                 : "r"(A0), "r"(A1), "r"(A2), "r"(A3), "r"(B0), "r"(B1))

#define CP16(smem_u32, gptr)                                                   \
    asm volatile("cp.async.cg.shared.global [%0], [%1], 16;"                   \
                 :: "r"(smem_u32), "l"(gptr))

// ---------------- RoPE cos/sin table ----------------------------------------
__global__ __launch_bounds__(256) void rope_table(float2* __restrict__ tab) {
    int idx = blockIdx.x * 256 + threadIdx.x;
    if (idx >= Ss * 32) return;
    int s = idx >> 5, p = idx & 31;
    double theta = pow(10000.0, -(2.0 * p) / 64.0);
    float ang = (float)((double)s * theta);
    float sn, cn;
    sincosf(ang, &sn, &cn);
    tab[idx] = make_float2(cn, sn);
}

// ---------------- TF32 tensor-core GEMM, cp.async double-buffered ----------
// (frozen since R8/R13/R14 — do not touch numerics)
template<bool PRECISE, int EPI>
__global__ __launch_bounds__(256, 2) void gemm_tc(const float* __restrict__ A,
                                                  const float* __restrict__ B,
                                                  float* __restrict__ C,
                                                  int M, int N, int K,
                                                  const float2* __restrict__ tab,
                                                  __half* __restrict__ kvp,
                                                  const float* __restrict__ B2,
                                                  float* __restrict__ C2) {
    __shared__ __align__(16) float As[2][128 * 20];
    __shared__ __align__(16) float Bs[2][16 * 136];
    int tid = threadIdx.x;
    int lane = tid & 31, warp = tid >> 5;
    int g = lane >> 2, tg = lane & 3;
    int wm0 = (warp & 1) * 64, wn0 = (warp >> 1) * 32;
    int m0 = blockIdx.y * 128, n0 = blockIdx.x * 128;

    const float* Bp = B;
    int Nb = (EPI == 1) ? 3072 : N;
    int nb0 = n0;
    if (EPI == 1 && n0 >= 3072) { Bp = B2; Nb = 256; nb0 = n0 - 3072; }

    unsigned sA0 = (unsigned)__cvta_generic_to_shared(&As[0][0]);
    unsigned sB0 = (unsigned)__cvta_generic_to_shared(&Bs[0][0]);

    float acc[4][4][4];
    #pragma unroll
    for (int mi = 0; mi < 4; mi++)
        #pragma unroll
        for (int nj = 0; nj < 4; nj++)
            #pragma unroll
            for (int q = 0; q < 4; q++) acc[mi][nj][q] = 0.f;

    const int nK = K / 16;

    #define LOAD_STAGE(st, k0)                                                 \
        do {                                                                   \
            _Pragma("unroll")                                                  \
            for (int it = 0; it < 2; it++) {                                   \
                int i = tid + it * 256;                                        \
                int r = i >> 2, kk = (i & 3) * 4;                              \
                CP16(sA0 + ((st) * 2560 + r * 20 + kk) * 4,                    \
                     A + (size_t)(m0 + r) * K + (k0) + kk);                    \
                int bk = i >> 5, n4 = (i & 31) * 4;                            \
                CP16(sB0 + ((st) * 2176 + bk * 136 + n4) * 4,                  \
                     Bp + (size_t)((k0) + bk) * Nb + nb0 + n4);                \
            }                                                                  \
        } while (0)

    LOAD_STAGE(0, 0);
    asm volatile("cp.async.commit_group;");

    for (int ks = 0; ks < nK; ks++) {
        int cur = ks & 1;
        if (ks + 1 < nK) {
            LOAD_STAGE(cur ^ 1, (ks + 1) * 16);
            asm volatile("cp.async.commit_group;");
            asm volatile("cp.async.wait_group 1;");
        } else {
            asm volatile("cp.async.wait_group 0;");
        }
        __syncthreads();

        const float* as = As[cur];
        const float* bs = Bs[cur];
        #pragma unroll
        for (int kc = 0; kc < 16; kc += 8) {
            unsigned ah[4][4], al[4][4];
            unsigned bh[4][2], bl[4][2];
            #pragma unroll
            for (int mi = 0; mi < 4; mi++) {
                int r = wm0 + mi * 16 + g;
                float v0 = as[r * 20 + kc + tg];
                float v1 = as[(r + 8) * 20 + kc + tg];
                float v2 = as[r * 20 + kc + tg + 4];
                float v3 = as[(r + 8) * 20 + kc + tg + 4];
                ah[mi][0] = t32h(v0); ah[mi][1] = t32h(v1);
                ah[mi][2] = t32h(v2); ah[mi][3] = t32h(v3);
                if (PRECISE) {
                    al[mi][0] = t32l(v0, ah[mi][0]); al[mi][1] = t32l(v1, ah[mi][1]);
                    al[mi][2] = t32l(v2, ah[mi][2]); al[mi][3] = t32l(v3, ah[mi][3]);
                }
            }
            #pragma unroll
            for (int nj = 0; nj < 4; nj++) {
                int c = wn0 + nj * 8 + g;
                float v0 = bs[(kc + tg) * 136 + c];
                float v1 = bs[(kc + tg + 4) * 136 + c];
                bh[nj][0] = t32h(v0); bh[nj][1] = t32h(v1);
                if (PRECISE) {
                    bl[nj][0] = t32l(v0, bh[nj][0]);
                    bl[nj][1] = t32l(v1, bh[nj][1]);
                }
            }
            #pragma unroll
            for (int mi = 0; mi < 4; mi++)
                #pragma unroll
                for (int nj = 0; nj < 4; nj++) {
                    MMA_TF32(acc[mi][nj], ah[mi][0], ah[mi][1], ah[mi][2], ah[mi][3],
                             bh[nj][0], bh[nj][1]);
                    if (PRECISE) {
                        MMA_TF32(acc[mi][nj], ah[mi][0], ah[mi][1], ah[mi][2], ah[mi][3],
                                 bl[nj][0], bl[nj][1]);
                        MMA_TF32(acc[mi][nj], al[mi][0], al[mi][1], al[mi][2], al[mi][3],
                                 bh[nj][0], bh[nj][1]);
                    }
                }
        }
        __syncthreads();
    }
    #undef LOAD_STAGE

    if (EPI == 0) {
        #pragma unroll
        for (int mi = 0; mi < 4; mi++) {
            int r = m0 + wm0 + mi * 16 + g;
            #pragma unroll
            for (int nj = 0; nj < 4; nj++) {
                int c = n0 + wn0 + nj * 8 + tg * 2;
                *(float2*)&C[(size_t)r * N + c] = make_float2(acc[mi][nj][0], acc[mi][nj][1]);
                *(float2*)&C[(size_t)(r + 8) * N + c] = make_float2(acc[mi][nj][2], acc[mi][nj][3]);
            }
        }
    } else {
        int region = n0 >> 10;   // 0=Q, 1=K, 2=V, 3=iq
        #pragma unroll
        for (int mi = 0; mi < 4; mi++) {
            int r = m0 + wm0 + mi * 16 + g;
            int s = r & 2047;
            #pragma unroll
            for (int nj = 0; nj < 4; nj++) {
                int c = n0 + wn0 + nj * 8 + tg * 2;
                float a0 = acc[mi][nj][0], a1 = acc[mi][nj][1];
                float a2 = acc[mi][nj][2], a3 = acc[mi][nj][3];
                if (region == 3) {
                    int cc = c - 3072;
                    *(float2*)&C2[(size_t)r * 256 + cc] = make_float2(a0, a1);
                    *(float2*)&C2[(size_t)(r + 8) * 256 + cc] = make_float2(a2, a3);
                } else if (region == 2) {
                    int cc = c & 1023;
                    *(__half2*)(kvp + (size_t)r * 2048 + 1024 + cc) = __floats2half2_rn(a0, a1);
                    *(__half2*)(kvp + (size_t)(r + 8) * 2048 + 1024 + cc) = __floats2half2_rn(a2, a3);
                } else {
                    int cc = c & 1023;
                    int p = (cc & 63) >> 1;
                    float2 t0 = tab[s * 32 + p];
                    float2 t1 = tab[(s + 8) * 32 + p];
                    float y0 = a0 * t0.x - a1 * t0.y;
                    float y1 = a1 * t0.x + a0 * t0.y;
                    float y2 = a2 * t1.x - a3 * t1.y;
                    float y3 = a3 * t1.x + a2 * t1.y;
                    if (region == 0) {
                        *(float2*)&C[(size_t)r * 1024 + cc] = make_float2(y0, y1);
                        *(float2*)&C[(size_t)(r + 8) * 1024 + cc] = make_float2(y2, y3);
                    } else {
                        *(__half2*)(kvp + (size_t)r * 2048 + cc) = __floats2half2_rn(y0, y1);
                        *(__half2*)(kvp + (size_t)(r + 8) * 2048 + cc) = __floats2half2_rn(y2, y3);
                    }
                }
            }
        }
    }
}

// ---------------- scalar fp32 SGEMM (exact) for fused ik|iw (R14) ----------
__global__ __launch_bounds__(256) void sgemm(const float* __restrict__ A,
                                             const float* __restrict__ B,
                                             float* __restrict__ C,
                                             int M, int N, int K) {
    __shared__ float As[64][17];
    __shared__ float Bs[16][64];
    int tid = threadIdx.x;
    int tx = tid & 15, ty = tid >> 4;
    int row0 = blockIdx.y * 64, col0 = blockIdx.x * 64;
    float acc[4][4] = {};
    for (int k0 = 0; k0 < K; k0 += 16) {
        #pragma unroll
        for (int i = 0; i < 4; i++) {
            int idx = tid + i * 256;
            int r = idx >> 4, kk = idx & 15;
            As[r][kk] = A[(size_t)(row0 + r) * K + k0 + kk];
        }
        #pragma unroll
        for (int i = 0; i < 4; i++) {
            int idx = tid + i * 256;
            int kk = idx >> 6, c = idx & 63;
            int col = col0 + c;
            Bs[kk][c] = (col < N) ? B[(size_t)(k0 + kk) * N + col] : 0.f;
        }
        __syncthreads();
        #pragma unroll
        for (int kk = 0; kk < 16; kk++) {
            float a[4], b[4];
            #pragma unroll
            for (int i = 0; i < 4; i++) a[i] = As[ty * 4 + i][kk];
            #pragma unroll
            for (int j = 0; j < 4; j++) b[j] = Bs[kk][tx * 4 + j];
            #pragma unroll
            for (int i = 0; i < 4; i++)
                #pragma unroll
                for (int j = 0; j < 4; j++)
                    acc[i][j] += a[i] * b[j];
        }
        __syncthreads();
    }
    #pragma unroll
    for (int i = 0; i < 4; i++) {
        int r = row0 + ty * 4 + i;
        #pragma unroll
        for (int j = 0; j < 4; j++) {
            int c = col0 + tx * 4 + j;
            if (c < N) C[(size_t)r * N + c] = acc[i][j];
        }
    }
}

// ---------------- pack Wk|Ww -> [1024, 68] ----------------------------------
__global__ __launch_bounds__(256) void pack_wkw(const float* __restrict__ Wk,
                                                const float* __restrict__ Ww,
                                                float* __restrict__ Wkw) {
    int idx = blockIdx.x * 256 + threadIdx.x;
    if (idx >= Dd * NKW) return;
    int row = idx / NKW, col = idx - row * NKW;
    Wkw[idx] = (col < 64) ? Wk[row * 64 + col] : Ww[row * IHh + (col - 64)];
}

__device__ __forceinline__ unsigned flipf(float f) {
    unsigned u = __float_as_uint(f);
    return (u & 0x80000000u) ? ~u : (u | 0x80000000u);
}

// ---------------- indexer scores + exact causal top-k ----------------------
// 4-pass radix with exact early-exit (whole-boundary-bin case) and a single
// merged final sweep. Selected SET identical to R14.
__global__ __launch_bounds__(256) void indexer_topk(const float* __restrict__ iq,
                                                    const float* __restrict__ ikw,
                                                    int* __restrict__ sel,
                                                    int* __restrict__ cnt) {
    int bt = blockIdx.x;
    int b = bt >> 11, t = bt & 2047;
    int tid = threadIdx.x;
    int lane = tid & 31, w = tid >> 5;
    int n = t + 1;

    __shared__ float sq[IHh * IDd];
    __shared__ float sw[IHh];
    if (tid < IHh * IDd) sq[tid] = iq[(size_t)bt * IHh * IDd + tid];
    if (tid < IHh) sw[tid] = ikw[(size_t)bt * NKW + 64 + tid];

    if (n <= TOPK) {
        for (int s = tid; s < n; s += 256) sel[(size_t)bt * TOPK + s] = s;
        if (tid == 0) cnt[bt] = n;
        return;
    }
    __syncthreads();

    __shared__ float sc[Ss];
    for (int s = tid; s < n; s += 256) {
        const float4* k4 = (const float4*)(ikw + (size_t)(b * Ss + s) * NKW);
        float d0 = 0.f, d1 = 0.f, d2 = 0.f, d3 = 0.f;
        #pragma unroll
        for (int j4 = 0; j4 < 16; j4++) {
            float4 kv = k4[j4];
            int o = j4 * 4;
            d0 += sq[0*64+o]*kv.x + sq[0*64+o+1]*kv.y + sq[0*64+o+2]*kv.z + sq[0*64+o+3]*kv.w;
            d1 += sq[1*64+o]*kv.x + sq[1*64+o+1]*kv.y + sq[1*64+o+2]*kv.z + sq[1*64+o+3]*kv.w;
            d2 += sq[2*64+o]*kv.x + sq[2*64+o+1]*kv.y + sq[2*64+o+2]*kv.z + sq[2*64+o+3]*kv.w;
            d3 += sq[3*64+o]*kv.x + sq[3*64+o+1]*kv.y + sq[3*64+o+2]*kv.z + sq[3*64+o+3]*kv.w;
        }
        sc[s] = sw[0]*fmaxf(d0,0.f) + sw[1]*fmaxf(d1,0.f)
              + sw[2]*fmaxf(d2,0.f) + sw[3]*fmaxf(d3,0.f);
    }
    __syncthreads();

    __shared__ int hist[256];
    __shared__ int sfx[256];
    __shared__ unsigned sh_prefix;
    __shared__ int sh_krem;
    __shared__ int sh_done;
    if (tid == 0) sh_done = 0;
    unsigned prefix = 0;
    int krem = TOPK;
    for (int pass = 0; pass < 4; pass++) {
        int shift = 24 - pass * 8;
        hist[tid] = 0;
        __syncthreads();
        for (int s0 = 0; s0 < n; s0 += 256) {
            int s = s0 + tid;
            bool valid = false;
            unsigned bin = 0;
            if (s < n) {
                unsigned key = flipf(sc[s]);
                if (((key >> shift) >> 8) == prefix) {
                    valid = true;
                    bin = (key >> shift) & 255;
                }
            }
            unsigned act = __ballot_sync(0xffffffffu, valid);
            if (valid) {
                unsigned peers = __match_any_sync(act, bin);
                if ((__ffs(peers) - 1) == lane)
                    atomicAdd(&hist[bin], __popc(peers));
            }
        }
        __syncthreads();
        sfx[tid] = hist[tid];
        __syncthreads();
        #pragma unroll
        for (int off = 1; off < 256; off <<= 1) {
            int add = (tid + off < 256) ? sfx[tid + off] : 0;
            __syncthreads();
            sfx[tid] += add;
            __syncthreads();
        }
        int sf = sfx[tid];
        int sfn = (tid < 255) ? sfx[tid + 1] : 0;
        if (sf >= krem && sfn < krem) {
            unsigned np = (prefix << 8) | (unsigned)tid;
            if (sf == krem && np != 0) {
                // whole boundary bin taken: threshold known now
                sh_prefix = (np << shift) - 1u;   // full 32-bit T
                sh_krem = 0;
                sh_done = 1;
            } else {
                sh_prefix = np;
                sh_krem = krem - sfn;
            }
        }
        __syncthreads();
        prefix = sh_prefix;
        krem = sh_krem;
        if (sh_done) break;
        __syncthreads();
    }
    unsigned T = prefix;   // full 32-bit threshold in both paths

    __shared__ int nsel;
    if (tid == 0) nsel = 0;
    __syncthreads();

    if (krem == 0) {
        // fast path: selection is exactly {key > T}; single sweep, no barriers
        for (int s = tid; s < n; s += 256) {
            if (flipf(sc[s]) > T) {
                int p = atomicAdd(&nsel, 1);
                sel[(size_t)bt * TOPK + p] = s;
            }
        }
    } else {
        // merged sweep: strictly-greater writes + equals rank-by-index
        __shared__ int warpcnt[8];
        __shared__ int eqbase;
        if (tid == 0) eqbase = 0;
        __syncthreads();
        for (int s0 = 0; s0 < n; s0 += 256) {
            int s = s0 + tid;
            unsigned key = (s < n) ? flipf(sc[s]) : 0u;
            bool gt = (s < n) && (key > T);
            bool eq = (s < n) && (key == T);
            if (gt) {
                int p = atomicAdd(&nsel, 1);
                sel[(size_t)bt * TOPK + p] = s;
            }
            unsigned bal = __ballot_sync(0xffffffffu, eq);
            if (lane == 0) warpcnt[w] = __popc(bal);
            __syncthreads();
            int wbase = 0;
            for (int i = 0; i < w; i++) wbase += warpcnt[i];
            int rank = eqbase + wbase + __popc(bal & ((1u << lane) - 1));
            if (eq && rank < krem) {
                int p = atomicAdd(&nsel, 1);
                sel[(size_t)bt * TOPK + p] = s;
            }
            __syncthreads();
            if (tid == 0) {
                int tot = 0;
                for (int i = 0; i < 8; i++) tot += warpcnt[i];
                eqbase += tot;
            }
            __syncthreads();
        }
    }
    if (tid == 0) cnt[bt] = TOPK;
}

// ---------------- sparse SDPA: block per (b,t, head-half), warp per head ---
__global__ __launch_bounds__(256, 2) void sdpa(const float* __restrict__ qp,
                                               const __half* __restrict__ kv,
                                               const int* __restrict__ sel,
                                               const int* __restrict__ cnt,
                                               float* __restrict__ attn) {
    int bt = blockIdx.x;
    int b = bt >> 11;
    int tid = threadIdx.x;
    int w = tid >> 5, lane = tid & 31;
    int h = blockIdx.y * 8 + w;

    __shared__ float sQ[8 * DHh];
    __shared__ int   sSel[TOPK];
    __shared__ float sL[8][TOPK];

    int n = cnt[bt];
    const float* Qrow = qp + (size_t)bt * Dd + blockIdx.y * 512;
    for (int i = tid; i < 512; i += 256) sQ[i] = Qrow[i];
    for (int i = tid; i < n; i += 256) sSel[i] = sel[(size_t)bt * TOPK + i];
    __syncthreads();

    float qr[64];
    #pragma unroll
    for (int i = 0; i < 64; i += 4) {
        float4 tq = *(const float4*)&sQ[w * 64 + i];
        qr[i] = tq.x; qr[i+1] = tq.y; qr[i+2] = tq.z; qr[i+3] = tq.w;
    }

    const float scale = 0.125f;
    size_t kvbase = (size_t)b * Ss * 2048;

    for (int j0 = 0; j0 < n; j0 += 32) {
        int j = j0 + lane;
        if (j < n) {
            int s = sSel[j];
            const uint4* kp = (const uint4*)(kv + kvbase + (size_t)s * 2048 + h * 64);
            float d = 0.f;
            #pragma unroll
            for (int i = 0; i < 8; i++) {
                uint4 wv = kp[i];
                const __half2* p2 = (const __half2*)&wv;
                #pragma unroll
                for (int q = 0; q < 4; q++) {
                    float2 f = __half22float2(p2[q]);
                    d += qr[i*8 + q*2] * f.x + qr[i*8 + q*2 + 1] * f.y;
                }
            }
            sL[w][j] = d * scale;
        }
    }
    __syncwarp();

    float m = -1e30f;
    for (int j = lane; j < n; j += 32) m = fmaxf(m, sL[w][j]);
    #pragma unroll
    for (int o = 16; o; o >>= 1) m = fmaxf(m, __shfl_xor_sync(0xffffffffu, m, o));
    float sum = 0.f;
    for (int j = lane; j < n; j += 32) {
        float p = __expf(sL[w][j] - m);
        sL[w][j] = p;
        sum += p;
    }
    #pragma unroll
    for (int o = 16; o; o >>= 1) sum += __shfl_xor_sync(0xffffffffu, sum, o);
    float inv = 1.f / sum;
    __syncwarp();

    int kg = lane >> 3, dg = lane & 7;
    float acc[8] = {};
    #pragma unroll 4
    for (int j0 = 0; j0 < n; j0 += 4) {
        int j = j0 + kg;
        if (j < n) {
            float p = sL[w][j];
            int s = sSel[j];
            uint4 vv = *(const uint4*)(kv + kvbase + (size_t)s * 2048 + 1024 + h * 64 + dg * 8);
            const __half2* h2 = (const __half2*)&vv;
            #pragma unroll
            for (int q = 0; q < 4; q++) {
                float2 f = __half22float2(h2[q]);
                acc[2*q]     += p * f.x;
                acc[2*q + 1] += p * f.y;
            }
        }
    }
    #pragma unroll
    for (int q = 0; q < 8; q++) {
        acc[q] += __shfl_xor_sync(0xffffffffu, acc[q], 8);
        acc[q] += __shfl_xor_sync(0xffffffffu, acc[q], 16);
    }
    if (kg == 0) {
        size_t ob = (size_t)bt * Dd + h * 64 + dg * 8;
        float4 o0 = make_float4(acc[0] * inv, acc[1] * inv, acc[2] * inv, acc[3] * inv);
        float4 o1 = make_float4(acc[4] * inv, acc[5] * inv, acc[6] * inv, acc[7] * inv);
        *(float4*)&attn[ob]     = o0;
        *(float4*)&attn[ob + 4] = o1;
    }
}

// ---------------- launch ----------------------------------------------------
extern "C" void kernel_launch(void* const* d_in, const int* in_sizes, int n_in,
                              void* d_out, int out_size) {
    const float* x      = (const float*)d_in[0];
    const float* W_qkv  = (const float*)d_in[1];
    const float* W_o    = (const float*)d_in[2];
    const float* Wq_idx = (const float*)d_in[3];
    const float* Wk_idx = (const float*)d_in[4];
    const float* Ww_idx = (const float*)d_in[5];
    float* out = (float*)d_out;

    float *qp, *iq, *wkw, *ikw, *attn;
    float2* tab;
    __half* kv;
    int *sel, *cnt;
    cudaGetSymbolAddress((void**)&qp,   g_q);
    cudaGetSymbolAddress((void**)&kv,   g_kv);
    cudaGetSymbolAddress((void**)&tab,  g_tab);
    cudaGetSymbolAddress((void**)&iq,   g_iq);
    cudaGetSymbolAddress((void**)&wkw,  g_wkw);
    cudaGetSymbolAddress((void**)&ikw,  g_ikw);
    cudaGetSymbolAddress((void**)&attn, g_attn);
    cudaGetSymbolAddress((void**)&sel,  g_sel);
    cudaGetSymbolAddress((void**)&cnt,  g_cnt);

    const int M = BT;  // 4096

    rope_table<<<(Ss * 32 + 255) / 256, 256>>>(tab);
    pack_wkw<<<(Dd * NKW + 255) / 256, 256>>>(Wk_idx, Ww_idx, wkw);
    // Fused QKV + iq projection, RoPE + fp16 K/V epilogue
    gemm_tc<true, 1><<<dim3(NFUSE / 128, M / 128), 256>>>(
        x, W_qkv, qp, M, NFUSE, Dd, tab, kv, Wq_idx, iq);
    // ik|iw fused projection: exact fp32 (R14 config — frozen selection numerics)
    sgemm<<<dim3(2, M / 64), 256>>>(x, wkw, ikw, M, NKW, Dd);
    // indexer scores + top-k selection (early-exit + merged sweep)
    indexer_topk<<<BT, 256>>>(iq, ikw, sel, cnt);
    // sparse attention
    sdpa<<<dim3(BT, 2), 256>>>(qp, kv, sel, cnt, attn);
    // output projection (3xTF32)
    gemm_tc<true, 0><<<dim3(Dd / 128, M / 128), 256>>>(
        attn, W_o, out, M, Dd, Dd, nullptr, nullptr, nullptr, nullptr);
}